// round 2
// baseline (speedup 1.0000x reference)
#include <cuda_runtime.h>
#include <math.h>

#define NN 10000
#define BB 4
#define EE 160000
#define MROWS 40000   // N*B rows

typedef unsigned long long ull;

// ---------------- static scratch (no runtime allocation) ----------------
__device__ __align__(128) int   g_counts[NN + 1];
__device__ __align__(128) int   g_off[NN + 1];
__device__ __align__(128) int   g_cursor[NN];
__device__ __align__(128) int   g_csr_src[EE];
__device__ __align__(128) float g_csr_w[EE];
__device__ __align__(128) float g_X[MROWS * 128];   // packed GEMM input
__device__ __align__(128) float g_T[MROWS * 384];   // GEMM output / agg workspace
__device__ __align__(128) float g_R[MROWS * 64];    // r gate, layout [n][b][64]
__device__ __align__(128) float g_U[MROWS * 64];    // u gate, layout [n][b][64]

// ---------------- CSR build ----------------
__global__ void zero_counts_kernel() {
    int i = blockIdx.x * blockDim.x + threadIdx.x;
    if (i <= NN) g_counts[i] = 0;
}

__global__ void hist_kernel(const int* __restrict__ dst) {
    int e = blockIdx.x * blockDim.x + threadIdx.x;
    if (e < EE) atomicAdd(&g_counts[dst[e]], 1);
}

// single-block scan over 10000 counts -> exclusive offsets + cursor copy
__global__ void scan_kernel() {
    __shared__ int s[1024];
    const int t = threadIdx.x;
    const int base = t * 10;
    int vals[10];
    int run = 0;
#pragma unroll
    for (int i = 0; i < 10; i++) {
        int idx = base + i;
        int c = (idx < NN) ? g_counts[idx] : 0;
        run += c;
        vals[i] = run;
    }
    s[t] = run;
    __syncthreads();
    for (int d = 1; d < 1024; d <<= 1) {
        int v = (t >= d) ? s[t - d] : 0;
        __syncthreads();
        s[t] += v;
        __syncthreads();
    }
    int excl = s[t] - run;
    if (t == 0) g_off[0] = 0;
#pragma unroll
    for (int i = 0; i < 10; i++) {
        int idx = base + i;
        if (idx < NN) {
            g_off[idx + 1]  = excl + vals[i];
            g_cursor[idx]   = excl + (i ? vals[i - 1] : 0);
        }
    }
}

__global__ void fill_kernel(const int* __restrict__ src, const int* __restrict__ dst,
                            const float* __restrict__ ker) {
    int e = blockIdx.x * blockDim.x + threadIdx.x;
    if (e < EE) {
        int d = dst[e];
        int p = atomicAdd(&g_cursor[d], 1);
        g_csr_src[p] = src[e];
        g_csr_w[p]   = ker[e];
    }
}

// ---------------- input packing (B-major -> node-major rows of 128) ----------------
__global__ void packA_kernel(const float* __restrict__ inputs, const float* __restrict__ hx) {
    int g = blockIdx.x * blockDim.x + threadIdx.x;  // one float4 each
    if (g >= MROWS * 32) return;
    int row = g >> 5;
    int k4  = (g & 31) * 4;
    int n = row >> 2, b = row & 3;
    float4 v;
    if (k4 < 64) v = *(const float4*)&inputs[(b * NN + n) * 64 + k4];
    else         v = *(const float4*)&hx[(b * NN + n) * 64 + (k4 - 64)];
    *(float4*)&g_X[row * 128 + k4] = v;
}

__global__ void packB_kernel(const float* __restrict__ inputs, const float* __restrict__ hx) {
    int g = blockIdx.x * blockDim.x + threadIdx.x;
    if (g >= MROWS * 32) return;
    int row = g >> 5;
    int k4  = (g & 31) * 4;
    int n = row >> 2, b = row & 3;
    float4 v;
    if (k4 < 64) {
        v = *(const float4*)&inputs[(b * NN + n) * 64 + k4];
    } else {
        float4 r4 = *(const float4*)&g_R[row * 64 + (k4 - 64)];
        float4 h4 = *(const float4*)&hx[(b * NN + n) * 64 + (k4 - 64)];
        v = make_float4(r4.x * h4.x, r4.y * h4.y, r4.z * h4.z, r4.w * h4.w);
    }
    *(float4*)&g_X[row * 128 + k4] = v;
}

// ---------------- GEMM v2: packed f32x2 FMA ----------------
// T[M x Ntot] = X[M x 128] @ Wcat[128 x Ntot], col-block = one view (NTILE == CO)
__device__ __forceinline__ void ffma2(ull& d, ull a, ull b) {
    asm("fma.rn.f32x2 %0, %1, %2, %0;" : "+l"(d) : "l"(a), "l"(b));
}

template <int NTILE>
__global__ void gemm2_kernel(const float* __restrict__ W, int Ntot) {
    constexpr int CPT = NTILE / 16;   // cols per thread (8 or 4)
    constexpr int CP2 = CPT / 2;      // col pairs per thread (4 or 2)
    __shared__ float As[16][256];     // row-duplicated A: As[k][2r]=As[k][2r+1]=a(r,k)
    __shared__ float Bs[16][NTILE];
    const int tid = threadIdx.x;
    const int tx = tid & 15;
    const int ty = tid >> 4;
    const int row0 = blockIdx.x * 128;
    const int v = blockIdx.y;         // view index == column block

    ull acc[8][CP2];
#pragma unroll
    for (int r = 0; r < 8; r++)
#pragma unroll
        for (int c = 0; c < CP2; c++) acc[r][c] = 0ull;  // packed (0.f, 0.f)

    for (int k0 = 0; k0 < 128; k0 += 16) {
        // A tile: 128 rows x 16 k, stored duplicated
#pragma unroll
        for (int u = 0; u < 2; u++) {
            int lin = tid * 2 + u;          // 0..511
            int r = lin >> 2;               // 0..127
            int kq = (lin & 3) * 4;         // 0,4,8,12
            int grow = row0 + r;
            float4 a = make_float4(0.f, 0.f, 0.f, 0.f);
            if (grow < MROWS) a = *(const float4*)&g_X[grow * 128 + k0 + kq];
            float av[4] = {a.x, a.y, a.z, a.w};
#pragma unroll
            for (int i = 0; i < 4; i++)
                *(float2*)&As[kq + i][2 * r] = make_float2(av[i], av[i]);
        }
        // B tile: 16 k x NTILE cols
#pragma unroll
        for (int u = 0; u < (16 * NTILE / 4) / 256; u++) {
            int idx = tid + u * 256;
            int k = idx / (NTILE / 4);
            int jl = (idx % (NTILE / 4)) * 4;
            float4 w = *(const float4*)&W[(v * 128 + k0 + k) * NTILE + jl];
            *(float4*)&Bs[k][jl] = w;
        }
        __syncthreads();
#pragma unroll
        for (int k = 0; k < 16; k++) {
            ull b[CP2];
#pragma unroll
            for (int c = 0; c < CP2; c++)
                b[c] = *(const ull*)&Bs[k][tx * CPT + 2 * c];
#pragma unroll
            for (int r = 0; r < 8; r++) {
                ull a = *(const ull*)&As[k][2 * (ty * 8 + r)];
#pragma unroll
                for (int c = 0; c < CP2; c++) ffma2(acc[r][c], a, b[c]);
            }
        }
        __syncthreads();
    }
#pragma unroll
    for (int r = 0; r < 8; r++) {
        int grow = row0 + ty * 8 + r;
        if (grow < MROWS) {
#pragma unroll
            for (int c = 0; c < CP2; c += 2) {
                __align__(16) ull t2[2] = {acc[r][c], acc[r][c + 1]};
                *(float4*)&g_T[grow * Ntot + v * NTILE + tx * CPT + 2 * c] = *(float4*)t2;
            }
        }
    }
}

// ---------------- sparse aggregation: one warp per node ----------------
template <int C, int MODE>
__global__ void agg_kernel(int rowStride, int srcOff, int initOff, int outOff,
                           const float* __restrict__ bias,
                           const float* __restrict__ hx,
                           float* __restrict__ out) {
    constexpr int V = (4 * C) / 128;  // float4s per lane
    const int warp = (blockIdx.x * blockDim.x + threadIdx.x) >> 5;
    const int lane = threadIdx.x & 31;
    if (warp >= NN) return;
    const int n = warp;

    int cq[V];
    int bq[V], jq[V];
#pragma unroll
    for (int q = 0; q < V; q++) {
        int f = 4 * lane + 128 * q;
        bq[q] = f / C;
        jq[q] = f % C;
        cq[q] = bq[q] * rowStride + jq[q];
    }

    float4 acc[V];
#pragma unroll
    for (int q = 0; q < V; q++)
        acc[q] = *(const float4*)&g_T[(n * 4) * rowStride + initOff + cq[q]];

    const int beg = g_off[n];
    const int end = g_off[n + 1];
    int i = beg;
    for (; i + 1 < end; i += 2) {
        int s0 = g_csr_src[i];
        int s1 = g_csr_src[i + 1];
        float w0 = g_csr_w[i];
        float w1 = g_csr_w[i + 1];
        const float* p0 = &g_T[(s0 * 4) * rowStride + srcOff];
        const float* p1 = &g_T[(s1 * 4) * rowStride + srcOff];
        float4 v0[V], v1[V];
#pragma unroll
        for (int q = 0; q < V; q++) v0[q] = *(const float4*)&p0[cq[q]];
#pragma unroll
        for (int q = 0; q < V; q++) v1[q] = *(const float4*)&p1[cq[q]];
#pragma unroll
        for (int q = 0; q < V; q++) {
            acc[q].x += w0 * v0[q].x + w1 * v1[q].x;
            acc[q].y += w0 * v0[q].y + w1 * v1[q].y;
            acc[q].z += w0 * v0[q].z + w1 * v1[q].z;
            acc[q].w += w0 * v0[q].w + w1 * v1[q].w;
        }
    }
    if (i < end) {
        int s0 = g_csr_src[i];
        float w0 = g_csr_w[i];
        const float* p0 = &g_T[(s0 * 4) * rowStride + srcOff];
#pragma unroll
        for (int q = 0; q < V; q++) {
            float4 v = *(const float4*)&p0[cq[q]];
            acc[q].x += w0 * v.x;
            acc[q].y += w0 * v.y;
            acc[q].z += w0 * v.z;
            acc[q].w += w0 * v.w;
        }
    }

    if (MODE == 0) {
#pragma unroll
        for (int q = 0; q < V; q++)
            *(float4*)&g_T[(n * 4) * rowStride + outOff + cq[q]] = acc[q];
    } else if (MODE == 1) {
        float4 b4 = *(const float4*)&bias[4 * lane];
#pragma unroll
        for (int q = 0; q < V; q++) {
            float4 s;
            s.x = 1.f / (1.f + expf(-(acc[q].x + b4.x)));
            s.y = 1.f / (1.f + expf(-(acc[q].y + b4.y)));
            s.z = 1.f / (1.f + expf(-(acc[q].z + b4.z)));
            s.w = 1.f / (1.f + expf(-(acc[q].w + b4.w)));
            int row = n * 4 + q;
            if (lane < 16) *(float4*)&g_R[row * 64 + 4 * lane] = s;
            else           *(float4*)&g_U[row * 64 + 4 * (lane - 16)] = s;
        }
    } else {  // MODE 2, C=64
        int j = (lane & 15) * 4;
        float4 b4 = *(const float4*)&bias[j];
#pragma unroll
        for (int q = 0; q < V; q++) {
            int b = bq[q];
            float4 c4;
            c4.x = tanhf(acc[q].x + b4.x);
            c4.y = tanhf(acc[q].y + b4.y);
            c4.z = tanhf(acc[q].z + b4.z);
            c4.w = tanhf(acc[q].w + b4.w);
            float4 u4 = *(const float4*)&g_U[(n * 4 + b) * 64 + j];
            float4 h4 = *(const float4*)&hx[(b * NN + n) * 64 + j];
            float4 o;
            o.x = u4.x * h4.x + (1.f - u4.x) * c4.x;
            o.y = u4.y * h4.y + (1.f - u4.y) * c4.y;
            o.z = u4.z * h4.z + (1.f - u4.z) * c4.z;
            o.w = u4.w * h4.w + (1.f - u4.w) * c4.w;
            *(float4*)&out[(b * NN + n) * 64 + j] = o;
        }
    }
}

// ---------------- launch ----------------
extern "C" void kernel_launch(void* const* d_in, const int* in_sizes, int n_in,
                              void* d_out, int out_size) {
    const float* inputs = (const float*)d_in[0];
    const float* hx     = (const float*)d_in[1];
    const int*   sidx   = (const int*)d_in[2];
    const float* ker    = (const float*)d_in[3];
    const float* W_ru   = (const float*)d_in[4];
    const float* b_ru   = (const float*)d_in[5];
    const float* W_c    = (const float*)d_in[6];
    const float* b_c    = (const float*)d_in[7];
    float* out = (float*)d_out;
    const int* src = sidx;
    const int* dst = sidx + EE;

    // CSR build
    zero_counts_kernel<<<(NN + 256) / 256, 256>>>();
    hist_kernel<<<(EE + 255) / 256, 256>>>(dst);
    scan_kernel<<<1, 1024>>>();
    fill_kernel<<<(EE + 255) / 256, 256>>>(src, dst, ker);

    const int packBlocks = (MROWS * 32 + 255) / 256;

    // ---- phase A: ru gates ----
    packA_kernel<<<packBlocks, 256>>>(inputs, hx);
    gemm2_kernel<128><<<dim3(313, 3), 256>>>(W_ru, 384);    // T = X @ [W0|W1|W2], 40000x384
    // t1 += A t2   (cols 128..255 <- init t1, gather t2 at cols 256..383)
    agg_kernel<128, 0><<<1250, 256>>>(384, 256, 128, 128, nullptr, nullptr, nullptr);
    // ru = sigmoid(t0 + A t1' + b_ru) -> R, U
    agg_kernel<128, 1><<<1250, 256>>>(384, 128, 0, 0, b_ru, nullptr, nullptr);

    // ---- phase B: candidate + GRU mix ----
    packB_kernel<<<packBlocks, 256>>>(inputs, hx);
    gemm2_kernel<64><<<dim3(313, 3), 256>>>(W_c, 192);      // T' = X' @ [W0'|W1'|W2'], 40000x192
    agg_kernel<64, 0><<<1250, 256>>>(192, 128, 64, 64, nullptr, nullptr, nullptr);
    agg_kernel<64, 2><<<1250, 256>>>(192, 64, 0, 0, b_c, hx, out);
}

// round 4
// speedup vs baseline: 1.2733x; 1.2733x over previous
#include <cuda_runtime.h>
#include <cuda_bf16.h>
#include <math.h>

#define NN 10000
#define BB 4
#define EE 160000
#define MROWS 40000   // N*B rows
#define MPAD  40064   // padded to 313*128

typedef unsigned long long ull;
typedef unsigned int uint;
typedef unsigned short ushort;

// ---------------- static scratch (no runtime allocation) ----------------
__device__ __align__(128) int   g_counts[NN + 1];
__device__ __align__(128) int   g_off[NN + 1];
__device__ __align__(128) int   g_cursor[NN];
__device__ __align__(128) int   g_csr_src[EE];
__device__ __align__(128) float g_csr_w[EE];
__device__ __align__(128) ushort g_Xs[2][(ull)MPAD * 128];   // bf16 hi/lo of X, [row][k]
__device__ __align__(128) uint4 g_Wruf[8 * 48 * 32];         // W_ru fragments [kt][n8][lane]
__device__ __align__(128) uint4 g_Wcf[8 * 24 * 32];          // W_c fragments
__device__ __align__(128) float g_T[(ull)MROWS * 384];       // GEMM out / agg workspace
__device__ __align__(128) float g_R[MROWS * 64];             // r gate [n][b][64]
__device__ __align__(128) float g_U[MROWS * 64];             // u gate [n][b][64]

// ---------------- helpers ----------------
__device__ __forceinline__ void split2(float a, ushort& hi, ushort& lo) {
    __nv_bfloat16 h = __float2bfloat16(a);
    __nv_bfloat16 l = __float2bfloat16(a - __bfloat162float(h));
    hi = *reinterpret_cast<ushort*>(&h);
    lo = *reinterpret_cast<ushort*>(&l);
}

__device__ __forceinline__ void mma_bf16(float* d, const uint* a, uint b0, uint b1) {
    asm volatile(
        "mma.sync.aligned.m16n8k16.row.col.f32.bf16.bf16.f32 "
        "{%0,%1,%2,%3}, {%4,%5,%6,%7}, {%8,%9}, {%0,%1,%2,%3};"
        : "+f"(d[0]), "+f"(d[1]), "+f"(d[2]), "+f"(d[3])
        : "r"(a[0]), "r"(a[1]), "r"(a[2]), "r"(a[3]), "r"(b0), "r"(b1));
}

// ---------------- CSR build ----------------
__global__ void zero_counts_kernel() {
    int i = blockIdx.x * blockDim.x + threadIdx.x;
    if (i <= NN) g_counts[i] = 0;
}

__global__ void hist_kernel(const int* __restrict__ dst) {
    int e = blockIdx.x * blockDim.x + threadIdx.x;
    if (e < EE) atomicAdd(&g_counts[dst[e]], 1);
}

__global__ void scan_kernel() {
    __shared__ int s[1024];
    const int t = threadIdx.x;
    const int base = t * 10;
    int vals[10];
    int run = 0;
#pragma unroll
    for (int i = 0; i < 10; i++) {
        int idx = base + i;
        int c = (idx < NN) ? g_counts[idx] : 0;
        run += c;
        vals[i] = run;
    }
    s[t] = run;
    __syncthreads();
    for (int d = 1; d < 1024; d <<= 1) {
        int v = (t >= d) ? s[t - d] : 0;
        __syncthreads();
        s[t] += v;
        __syncthreads();
    }
    int excl = s[t] - run;
    if (t == 0) g_off[0] = 0;
#pragma unroll
    for (int i = 0; i < 10; i++) {
        int idx = base + i;
        if (idx < NN) {
            g_off[idx + 1]  = excl + vals[i];
            g_cursor[idx]   = excl + (i ? vals[i - 1] : 0);
        }
    }
}

__global__ void fill_kernel(const int* __restrict__ src, const int* __restrict__ dst,
                            const float* __restrict__ ker) {
    int e = blockIdx.x * blockDim.x + threadIdx.x;
    if (e < EE) {
        int d = dst[e];
        int p = atomicAdd(&g_cursor[d], 1);
        g_csr_src[p] = src[e];
        g_csr_w[p]   = ker[e];
    }
}

// ---------------- input packing: B-major fp32 -> node-major bf16 hi/lo ----------------
__global__ void packA_kernel(const float* __restrict__ inputs, const float* __restrict__ hx) {
    int g = blockIdx.x * blockDim.x + threadIdx.x;  // one float4 each
    if (g >= MROWS * 32) return;
    int row = g >> 5;
    int k4  = (g & 31) * 4;
    int n = row >> 2, b = row & 3;
    float4 v;
    if (k4 < 64) v = *(const float4*)&inputs[(b * NN + n) * 64 + k4];
    else         v = *(const float4*)&hx[(b * NN + n) * 64 + (k4 - 64)];
    float av[4] = {v.x, v.y, v.z, v.w};
    ushort4 oh, ol;
    ushort* ph = &oh.x;
    ushort* pl = &ol.x;
#pragma unroll
    for (int i = 0; i < 4; i++) split2(av[i], ph[i], pl[i]);
    ull base = (ull)row * 128 + k4;
    *(ushort4*)&g_Xs[0][base] = oh;
    *(ushort4*)&g_Xs[1][base] = ol;
}

__global__ void packB_kernel(const float* __restrict__ inputs, const float* __restrict__ hx) {
    int g = blockIdx.x * blockDim.x + threadIdx.x;
    if (g >= MROWS * 32) return;
    int row = g >> 5;
    int k4  = (g & 31) * 4;
    int n = row >> 2, b = row & 3;
    float4 v;
    if (k4 < 64) {
        v = *(const float4*)&inputs[(b * NN + n) * 64 + k4];
    } else {
        float4 r4 = *(const float4*)&g_R[row * 64 + (k4 - 64)];
        float4 h4 = *(const float4*)&hx[(b * NN + n) * 64 + (k4 - 64)];
        v = make_float4(r4.x * h4.x, r4.y * h4.y, r4.z * h4.z, r4.w * h4.w);
    }
    float av[4] = {v.x, v.y, v.z, v.w};
    ushort4 oh, ol;
    ushort* ph = &oh.x;
    ushort* pl = &ol.x;
#pragma unroll
    for (int i = 0; i < 4; i++) split2(av[i], ph[i], pl[i]);
    ull base = (ull)row * 128 + k4;
    *(ushort4*)&g_Xs[0][base] = oh;
    *(ushort4*)&g_Xs[1][base] = ol;
}

// ---------------- W -> fragment-order split (tiny, once per launch) ----------------
// frag word (16B) at [kt][n8][lane= (n%8)*4+ksub]:
//   {hi(k0,k0+1), hi(k0+8,k0+9), lo(k0,k0+1), lo(k0+8,k0+9)}, k0 = kt*16+ksub*2
__global__ void wfrag_kernel(const float* __restrict__ W_ru, const float* __restrict__ W_c) {
    int idx = blockIdx.x * blockDim.x + threadIdx.x;
    const int T1 = 8 * 384 * 4;
    const int T2 = 8 * 192 * 4;
    if (idx < T1) {
        int kt = idx / (384 * 4);
        int rem = idx % (384 * 4);
        int n = rem >> 2, ksub = rem & 3;
        int v = n >> 7, j = n & 127;
        int k0 = kt * 16 + ksub * 2;
        float w0 = W_ru[(v * 128 + k0) * 128 + j];
        float w1 = W_ru[(v * 128 + k0 + 1) * 128 + j];
        float w8 = W_ru[(v * 128 + k0 + 8) * 128 + j];
        float w9 = W_ru[(v * 128 + k0 + 9) * 128 + j];
        ushort h0, l0, h1, l1, h8, l8, h9, l9;
        split2(w0, h0, l0); split2(w1, h1, l1);
        split2(w8, h8, l8); split2(w9, h9, l9);
        uint4 o;
        o.x = (uint)h0 | ((uint)h1 << 16);
        o.y = (uint)h8 | ((uint)h9 << 16);
        o.z = (uint)l0 | ((uint)l1 << 16);
        o.w = (uint)l8 | ((uint)l9 << 16);
        g_Wruf[(kt * 48 + (n >> 3)) * 32 + (n & 7) * 4 + ksub] = o;
    } else if (idx < T1 + T2) {
        int i2 = idx - T1;
        int kt = i2 / (192 * 4);
        int rem = i2 % (192 * 4);
        int n = rem >> 2, ksub = rem & 3;
        int v = n >> 6, j = n & 63;
        int k0 = kt * 16 + ksub * 2;
        float w0 = W_c[(v * 128 + k0) * 64 + j];
        float w1 = W_c[(v * 128 + k0 + 1) * 64 + j];
        float w8 = W_c[(v * 128 + k0 + 8) * 64 + j];
        float w9 = W_c[(v * 128 + k0 + 9) * 64 + j];
        ushort h0, l0, h1, l1, h8, l8, h9, l9;
        split2(w0, h0, l0); split2(w1, h1, l1);
        split2(w8, h8, l8); split2(w9, h9, l9);
        uint4 o;
        o.x = (uint)h0 | ((uint)h1 << 16);
        o.y = (uint)h8 | ((uint)h9 << 16);
        o.z = (uint)l0 | ((uint)l1 << 16);
        o.w = (uint)l8 | ((uint)l9 << 16);
        g_Wcf[(kt * 24 + (n >> 3)) * 32 + (n & 7) * 4 + ksub] = o;
    }
}

// ---------------- HMMA GEMM: T[M x 3*NTILE] = X @ Wcat, bf16x2 split (3 terms) ----------
// CTA: 128 rows x NTILE cols (one view). 8 warps: wy=wid>>1 (32 rows), wx=wid&1 (NTILE/2 cols).
template <int NTILE>
__global__ __launch_bounds__(256, 1) void mma_gemm() {
    constexpr int NB = NTILE / 16;       // n8-blocks per warp
    constexpr int N8TOT = (NTILE == 128) ? 48 : 24;
    constexpr int NTOT = 3 * NTILE;
    constexpr int ASPLIT = 128 * 272;    // bytes per A split (272B padded rows)
    constexpr int SL = (NTILE / 8) * 32; // uint4 per k-tile of B

    extern __shared__ __align__(16) char smem[];
    uint4* Bf = (uint4*)(smem + 2 * ASPLIT);

    const int tid = threadIdx.x;
    const int wid = tid >> 5, lane = tid & 31;
    const int wx = wid & 1, wy = wid >> 1;
    const int row0 = blockIdx.x * 128;
    const int v = blockIdx.y;

    // stage A: straight copy, 272B padded rows (conflict-free frag LDS later)
    for (int it = tid; it < 2 * 128 * 16; it += 256) {
        int s = it >> 11, rem = it & 2047;
        int m = rem >> 4, q = rem & 15;
        uint4 val = *(const uint4*)&g_Xs[s][(ull)(row0 + m) * 128 + q * 8];
        *(uint4*)(smem + s * ASPLIT + m * 272 + q * 16) = val;
    }
    // stage B: contiguous fragment slice for this view
    const uint4* WF = (NTILE == 128) ? g_Wruf : g_Wcf;
    const int vbase = v * (NTILE / 8);
    for (int it = tid; it < 8 * SL; it += 256) {
        int kt = it / SL, rem = it % SL;
        Bf[it] = WF[(kt * N8TOT + vbase) * 32 + rem];
    }
    __syncthreads();

    float acc[2][NB][4];
#pragma unroll
    for (int mb = 0; mb < 2; mb++)
#pragma unroll
        for (int nb = 0; nb < NB; nb++)
#pragma unroll
            for (int i = 0; i < 4; i++) acc[mb][nb][i] = 0.f;

#pragma unroll
    for (int kt = 0; kt < 8; kt++) {
        uint ah[2][4], al[2][4];
#pragma unroll
        for (int mb = 0; mb < 2; mb++) {
            int m = wy * 32 + mb * 16 + (lane >> 2);
            int boff = m * 272 + (kt * 16 + (lane & 3) * 2) * 2;
            ah[mb][0] = *(const uint*)(smem + boff);
            ah[mb][1] = *(const uint*)(smem + boff + 8 * 272);
            ah[mb][2] = *(const uint*)(smem + boff + 16);
            ah[mb][3] = *(const uint*)(smem + boff + 8 * 272 + 16);
            al[mb][0] = *(const uint*)(smem + ASPLIT + boff);
            al[mb][1] = *(const uint*)(smem + ASPLIT + boff + 8 * 272);
            al[mb][2] = *(const uint*)(smem + ASPLIT + boff + 16);
            al[mb][3] = *(const uint*)(smem + ASPLIT + boff + 8 * 272 + 16);
        }
#pragma unroll
        for (int nb = 0; nb < NB; nb++) {
            uint4 b = Bf[(kt * (NTILE / 8) + wx * NB + nb) * 32 + lane];
#pragma unroll
            for (int mb = 0; mb < 2; mb++) {
                mma_bf16(acc[mb][nb], ah[mb], b.x, b.y);   // hi*hi
                mma_bf16(acc[mb][nb], ah[mb], b.z, b.w);   // hi*lo
                mma_bf16(acc[mb][nb], al[mb], b.x, b.y);   // lo*hi
            }
        }
    }

    // epilogue
#pragma unroll
    for (int mb = 0; mb < 2; mb++) {
        int r = row0 + wy * 32 + mb * 16 + (lane >> 2);
#pragma unroll
        for (int nb = 0; nb < NB; nb++) {
            int c = v * NTILE + wx * (NTILE / 2) + nb * 8 + (lane & 3) * 2;
            if (r < MROWS)
                *(float2*)&g_T[(ull)r * NTOT + c] = make_float2(acc[mb][nb][0], acc[mb][nb][1]);
            if (r + 8 < MROWS)
                *(float2*)&g_T[(ull)(r + 8) * NTOT + c] = make_float2(acc[mb][nb][2], acc[mb][nb][3]);
        }
    }
}

// ---------------- sparse aggregation: one warp per node ----------------
template <int C, int MODE>
__global__ void agg_kernel(int rowStride, int srcOff, int initOff, int outOff,
                           const float* __restrict__ bias,
                           const float* __restrict__ hx,
                           float* __restrict__ out) {
    constexpr int V = (4 * C) / 128;
    const int warp = (blockIdx.x * blockDim.x + threadIdx.x) >> 5;
    const int lane = threadIdx.x & 31;
    if (warp >= NN) return;
    const int n = warp;

    int cq[V];
    int bq[V];
#pragma unroll
    for (int q = 0; q < V; q++) {
        int f = 4 * lane + 128 * q;
        bq[q] = f / C;
        cq[q] = bq[q] * rowStride + (f % C);
    }

    float4 acc[V];
#pragma unroll
    for (int q = 0; q < V; q++)
        acc[q] = *(const float4*)&g_T[(ull)(n * 4) * rowStride + initOff + cq[q]];

    const int beg = g_off[n];
    const int end = g_off[n + 1];
    int i = beg;
    for (; i + 1 < end; i += 2) {
        int s0 = g_csr_src[i];
        int s1 = g_csr_src[i + 1];
        float w0 = g_csr_w[i];
        float w1 = g_csr_w[i + 1];
        const float* p0 = &g_T[(ull)(s0 * 4) * rowStride + srcOff];
        const float* p1 = &g_T[(ull)(s1 * 4) * rowStride + srcOff];
        float4 v0[V], v1[V];
#pragma unroll
        for (int q = 0; q < V; q++) v0[q] = *(const float4*)&p0[cq[q]];
#pragma unroll
        for (int q = 0; q < V; q++) v1[q] = *(const float4*)&p1[cq[q]];
#pragma unroll
        for (int q = 0; q < V; q++) {
            acc[q].x += w0 * v0[q].x + w1 * v1[q].x;
            acc[q].y += w0 * v0[q].y + w1 * v1[q].y;
            acc[q].z += w0 * v0[q].z + w1 * v1[q].z;
            acc[q].w += w0 * v0[q].w + w1 * v1[q].w;
        }
    }
    if (i < end) {
        int s0 = g_csr_src[i];
        float w0 = g_csr_w[i];
        const float* p0 = &g_T[(ull)(s0 * 4) * rowStride + srcOff];
#pragma unroll
        for (int q = 0; q < V; q++) {
            float4 v = *(const float4*)&p0[cq[q]];
            acc[q].x += w0 * v.x;
            acc[q].y += w0 * v.y;
            acc[q].z += w0 * v.z;
            acc[q].w += w0 * v.w;
        }
    }

    if (MODE == 0) {
#pragma unroll
        for (int q = 0; q < V; q++)
            *(float4*)&g_T[(ull)(n * 4) * rowStride + outOff + cq[q]] = acc[q];
    } else if (MODE == 1) {
        float4 b4 = *(const float4*)&bias[4 * lane];
#pragma unroll
        for (int q = 0; q < V; q++) {
            float4 s;
            s.x = 1.f / (1.f + expf(-(acc[q].x + b4.x)));
            s.y = 1.f / (1.f + expf(-(acc[q].y + b4.y)));
            s.z = 1.f / (1.f + expf(-(acc[q].z + b4.z)));
            s.w = 1.f / (1.f + expf(-(acc[q].w + b4.w)));
            int row = n * 4 + q;
            if (lane < 16) *(float4*)&g_R[row * 64 + 4 * lane] = s;
            else           *(float4*)&g_U[row * 64 + 4 * (lane - 16)] = s;
        }
    } else {  // MODE 2, C=64
        int j = (lane & 15) * 4;
        float4 b4 = *(const float4*)&bias[j];
#pragma unroll
        for (int q = 0; q < V; q++) {
            int b = bq[q];
            float4 c4;
            c4.x = tanhf(acc[q].x + b4.x);
            c4.y = tanhf(acc[q].y + b4.y);
            c4.z = tanhf(acc[q].z + b4.z);
            c4.w = tanhf(acc[q].w + b4.w);
            float4 u4 = *(const float4*)&g_U[(n * 4 + b) * 64 + j];
            float4 h4 = *(const float4*)&hx[(b * NN + n) * 64 + j];
            float4 o;
            o.x = u4.x * h4.x + (1.f - u4.x) * c4.x;
            o.y = u4.y * h4.y + (1.f - u4.y) * c4.y;
            o.z = u4.z * h4.z + (1.f - u4.z) * c4.z;
            o.w = u4.w * h4.w + (1.f - u4.w) * c4.w;
            *(float4*)&out[(b * NN + n) * 64 + j] = o;
        }
    }
}

// ---------------- launch ----------------
extern "C" void kernel_launch(void* const* d_in, const int* in_sizes, int n_in,
                              void* d_out, int out_size) {
    const float* inputs = (const float*)d_in[0];
    const float* hx     = (const float*)d_in[1];
    const int*   sidx   = (const int*)d_in[2];
    const float* ker    = (const float*)d_in[3];
    const float* W_ru   = (const float*)d_in[4];
    const float* b_ru   = (const float*)d_in[5];
    const float* W_c    = (const float*)d_in[6];
    const float* b_c    = (const float*)d_in[7];
    float* out = (float*)d_out;
    const int* src = sidx;
    const int* dst = sidx + EE;

    const int SMEM_A = 2 * 128 * 272 + 8 * 16 * 32 * 16;  // 69632 + 65536 = 135168
    const int SMEM_B = 2 * 128 * 272 + 8 * 8 * 32 * 16;   // 69632 + 32768 = 102400
    cudaFuncSetAttribute(mma_gemm<128>, cudaFuncAttributeMaxDynamicSharedMemorySize, SMEM_A);
    cudaFuncSetAttribute(mma_gemm<64>,  cudaFuncAttributeMaxDynamicSharedMemorySize, SMEM_B);

    // CSR build
    zero_counts_kernel<<<(NN + 256) / 256, 256>>>();
    hist_kernel<<<(EE + 255) / 256, 256>>>(dst);
    scan_kernel<<<1, 1024>>>();
    fill_kernel<<<(EE + 255) / 256, 256>>>(src, dst, ker);

    // W fragment preprocessing
    wfrag_kernel<<<(8 * 384 * 4 + 8 * 192 * 4 + 255) / 256, 256>>>(W_ru, W_c);

    const int packBlocks = (MROWS * 32 + 255) / 256;

    // ---- phase A: ru gates ----
    packA_kernel<<<packBlocks, 256>>>(inputs, hx);
    mma_gemm<128><<<dim3(313, 3), 256, SMEM_A>>>();         // T = X @ [W0|W1|W2], 40000x384
    agg_kernel<128, 0><<<1250, 256>>>(384, 256, 128, 128, nullptr, nullptr, nullptr);
    agg_kernel<128, 1><<<1250, 256>>>(384, 128, 0, 0, b_ru, nullptr, nullptr);

    // ---- phase B: candidate + GRU mix ----
    packB_kernel<<<packBlocks, 256>>>(inputs, hx);
    mma_gemm<64><<<dim3(313, 3), 256, SMEM_B>>>();          // T' = X' @ [W0'|W1'|W2'], 40000x192
    agg_kernel<64, 0><<<1250, 256>>>(192, 128, 64, 64, nullptr, nullptr, nullptr);
    agg_kernel<64, 2><<<1250, 256>>>(192, 64, 0, 0, b_c, hx, out);
}

// round 5
// speedup vs baseline: 1.4025x; 1.1014x over previous
#include <cuda_runtime.h>
#include <cuda_bf16.h>
#include <cuda_fp16.h>
#include <math.h>

#define NN 10000
#define BB 4
#define EE 160000
#define MROWS 40000   // N*B rows
#define MPAD  40064   // padded to 313*128

typedef unsigned long long ull;
typedef unsigned int uint;
typedef unsigned short ushort;

// ---------------- static scratch (no runtime allocation) ----------------
__device__ __align__(128) int   g_counts[NN + 1];
__device__ __align__(128) int   g_off[NN + 1];
__device__ __align__(128) int   g_cursor[NN];
__device__ __align__(128) int   g_csr_src[EE];
__device__ __align__(128) float g_csr_w[EE];
__device__ __align__(128) ushort g_Xs[2][(ull)MPAD * 128];   // bf16 hi/lo of X, [row][k]
__device__ __align__(128) uint4 g_Wruf[8 * 48 * 32];         // W_ru fragments [kt][n8][lane]
__device__ __align__(128) uint4 g_Wcf[8 * 24 * 32];          // W_c fragments
__device__ __align__(128) __half g_T[(ull)MROWS * 384];      // GEMM out / agg workspace (fp16)
__device__ __align__(128) float g_U[MROWS * 64];             // u gate [n][b][64]

// ---------------- helpers ----------------
__device__ __forceinline__ void split2(float a, ushort& hi, ushort& lo) {
    __nv_bfloat16 h = __float2bfloat16(a);
    __nv_bfloat16 l = __float2bfloat16(a - __bfloat162float(h));
    hi = *reinterpret_cast<ushort*>(&h);
    lo = *reinterpret_cast<ushort*>(&l);
}

__device__ __forceinline__ void mma_bf16(float* d, const uint* a, uint b0, uint b1) {
    asm volatile(
        "mma.sync.aligned.m16n8k16.row.col.f32.bf16.bf16.f32 "
        "{%0,%1,%2,%3}, {%4,%5,%6,%7}, {%8,%9}, {%0,%1,%2,%3};"
        : "+f"(d[0]), "+f"(d[1]), "+f"(d[2]), "+f"(d[3])
        : "r"(a[0]), "r"(a[1]), "r"(a[2]), "r"(a[3]), "r"(b0), "r"(b1));
}

__device__ __forceinline__ void unpack8(uint4 v, float* f) {
    const __half2* h = reinterpret_cast<const __half2*>(&v);
#pragma unroll
    for (int i = 0; i < 4; i++) {
        float2 t = __half22float2(h[i]);
        f[2 * i] = t.x;
        f[2 * i + 1] = t.y;
    }
}

// ---------------- CSR build ----------------
__global__ void zero_counts_kernel() {
    int i = blockIdx.x * blockDim.x + threadIdx.x;
    if (i <= NN) g_counts[i] = 0;
}

__global__ void hist_kernel(const int* __restrict__ dst) {
    int e = blockIdx.x * blockDim.x + threadIdx.x;
    if (e < EE) atomicAdd(&g_counts[dst[e]], 1);
}

__global__ void scan_kernel() {
    __shared__ int s[1024];
    const int t = threadIdx.x;
    const int base = t * 10;
    int vals[10];
    int run = 0;
#pragma unroll
    for (int i = 0; i < 10; i++) {
        int idx = base + i;
        int c = (idx < NN) ? g_counts[idx] : 0;
        run += c;
        vals[i] = run;
    }
    s[t] = run;
    __syncthreads();
    for (int d = 1; d < 1024; d <<= 1) {
        int v = (t >= d) ? s[t - d] : 0;
        __syncthreads();
        s[t] += v;
        __syncthreads();
    }
    int excl = s[t] - run;
    if (t == 0) g_off[0] = 0;
#pragma unroll
    for (int i = 0; i < 10; i++) {
        int idx = base + i;
        if (idx < NN) {
            g_off[idx + 1]  = excl + vals[i];
            g_cursor[idx]   = excl + (i ? vals[i - 1] : 0);
        }
    }
}

__global__ void fill_kernel(const int* __restrict__ src, const int* __restrict__ dst,
                            const float* __restrict__ ker) {
    int e = blockIdx.x * blockDim.x + threadIdx.x;
    if (e < EE) {
        int d = dst[e];
        int p = atomicAdd(&g_cursor[d], 1);
        g_csr_src[p] = src[e];
        g_csr_w[p]   = ker[e];
    }
}

// ---------------- input packing: B-major fp32 -> node-major bf16 hi/lo ----------------
__global__ void packA_kernel(const float* __restrict__ inputs, const float* __restrict__ hx) {
    int g = blockIdx.x * blockDim.x + threadIdx.x;  // one float4 each
    if (g >= MROWS * 32) return;
    int row = g >> 5;
    int k4  = (g & 31) * 4;
    int n = row >> 2, b = row & 3;
    float4 v;
    if (k4 < 64) v = *(const float4*)&inputs[(b * NN + n) * 64 + k4];
    else         v = *(const float4*)&hx[(b * NN + n) * 64 + (k4 - 64)];
    float av[4] = {v.x, v.y, v.z, v.w};
    ushort4 oh, ol;
    ushort* ph = &oh.x;
    ushort* pl = &ol.x;
#pragma unroll
    for (int i = 0; i < 4; i++) split2(av[i], ph[i], pl[i]);
    ull base = (ull)row * 128 + k4;
    *(ushort4*)&g_Xs[0][base] = oh;
    *(ushort4*)&g_Xs[1][base] = ol;
}

// ---------------- W -> fragment-order split (tiny, once per launch) ----------------
__global__ void wfrag_kernel(const float* __restrict__ W_ru, const float* __restrict__ W_c) {
    int idx = blockIdx.x * blockDim.x + threadIdx.x;
    const int T1 = 8 * 384 * 4;
    const int T2 = 8 * 192 * 4;
    if (idx < T1) {
        int kt = idx / (384 * 4);
        int rem = idx % (384 * 4);
        int n = rem >> 2, ksub = rem & 3;
        int v = n >> 7, j = n & 127;
        int k0 = kt * 16 + ksub * 2;
        float w0 = W_ru[(v * 128 + k0) * 128 + j];
        float w1 = W_ru[(v * 128 + k0 + 1) * 128 + j];
        float w8 = W_ru[(v * 128 + k0 + 8) * 128 + j];
        float w9 = W_ru[(v * 128 + k0 + 9) * 128 + j];
        ushort h0, l0, h1, l1, h8, l8, h9, l9;
        split2(w0, h0, l0); split2(w1, h1, l1);
        split2(w8, h8, l8); split2(w9, h9, l9);
        uint4 o;
        o.x = (uint)h0 | ((uint)h1 << 16);
        o.y = (uint)h8 | ((uint)h9 << 16);
        o.z = (uint)l0 | ((uint)l1 << 16);
        o.w = (uint)l8 | ((uint)l9 << 16);
        g_Wruf[(kt * 48 + (n >> 3)) * 32 + (n & 7) * 4 + ksub] = o;
    } else if (idx < T1 + T2) {
        int i2 = idx - T1;
        int kt = i2 / (192 * 4);
        int rem = i2 % (192 * 4);
        int n = rem >> 2, ksub = rem & 3;
        int v = n >> 6, j = n & 63;
        int k0 = kt * 16 + ksub * 2;
        float w0 = W_c[(v * 128 + k0) * 64 + j];
        float w1 = W_c[(v * 128 + k0 + 1) * 64 + j];
        float w8 = W_c[(v * 128 + k0 + 8) * 64 + j];
        float w9 = W_c[(v * 128 + k0 + 9) * 64 + j];
        ushort h0, l0, h1, l1, h8, l8, h9, l9;
        split2(w0, h0, l0); split2(w1, h1, l1);
        split2(w8, h8, l8); split2(w9, h9, l9);
        uint4 o;
        o.x = (uint)h0 | ((uint)h1 << 16);
        o.y = (uint)h8 | ((uint)h9 << 16);
        o.z = (uint)l0 | ((uint)l1 << 16);
        o.w = (uint)l8 | ((uint)l9 << 16);
        g_Wcf[(kt * 24 + (n >> 3)) * 32 + (n & 7) * 4 + ksub] = o;
    }
}

// ---------------- HMMA GEMM: T[M x 3*NTILE] = X @ Wcat, bf16x2 split (3 terms) ----------
template <int NTILE>
__global__ __launch_bounds__(256, 1) void mma_gemm() {
    constexpr int NB = NTILE / 16;       // n8-blocks per warp
    constexpr int N8TOT = (NTILE == 128) ? 48 : 24;
    constexpr int NTOT = 3 * NTILE;
    constexpr int ASPLIT = 128 * 272;    // bytes per A split (272B padded rows)
    constexpr int SL = (NTILE / 8) * 32; // uint4 per k-tile of B

    extern __shared__ __align__(16) char smem[];
    uint4* Bf = (uint4*)(smem + 2 * ASPLIT);

    const int tid = threadIdx.x;
    const int wid = tid >> 5, lane = tid & 31;
    const int wx = wid & 1, wy = wid >> 1;
    const int row0 = blockIdx.x * 128;
    const int v = blockIdx.y;

    // stage A
    for (int it = tid; it < 2 * 128 * 16; it += 256) {
        int s = it >> 11, rem = it & 2047;
        int m = rem >> 4, q = rem & 15;
        uint4 val = *(const uint4*)&g_Xs[s][(ull)(row0 + m) * 128 + q * 8];
        *(uint4*)(smem + s * ASPLIT + m * 272 + q * 16) = val;
    }
    // stage B
    const uint4* WF = (NTILE == 128) ? g_Wruf : g_Wcf;
    const int vbase = v * (NTILE / 8);
    for (int it = tid; it < 8 * SL; it += 256) {
        int kt = it / SL, rem = it % SL;
        Bf[it] = WF[(kt * N8TOT + vbase) * 32 + rem];
    }
    __syncthreads();

    float acc[2][NB][4];
#pragma unroll
    for (int mb = 0; mb < 2; mb++)
#pragma unroll
        for (int nb = 0; nb < NB; nb++)
#pragma unroll
            for (int i = 0; i < 4; i++) acc[mb][nb][i] = 0.f;

#pragma unroll
    for (int kt = 0; kt < 8; kt++) {
        uint ah[2][4], al[2][4];
#pragma unroll
        for (int mb = 0; mb < 2; mb++) {
            int m = wy * 32 + mb * 16 + (lane >> 2);
            int boff = m * 272 + (kt * 16 + (lane & 3) * 2) * 2;
            ah[mb][0] = *(const uint*)(smem + boff);
            ah[mb][1] = *(const uint*)(smem + boff + 8 * 272);
            ah[mb][2] = *(const uint*)(smem + boff + 16);
            ah[mb][3] = *(const uint*)(smem + boff + 8 * 272 + 16);
            al[mb][0] = *(const uint*)(smem + ASPLIT + boff);
            al[mb][1] = *(const uint*)(smem + ASPLIT + boff + 8 * 272);
            al[mb][2] = *(const uint*)(smem + ASPLIT + boff + 16);
            al[mb][3] = *(const uint*)(smem + ASPLIT + boff + 8 * 272 + 16);
        }
#pragma unroll
        for (int nb = 0; nb < NB; nb++) {
            uint4 b = Bf[(kt * (NTILE / 8) + wx * NB + nb) * 32 + lane];
#pragma unroll
            for (int mb = 0; mb < 2; mb++) {
                mma_bf16(acc[mb][nb], ah[mb], b.x, b.y);   // hi*hi
                mma_bf16(acc[mb][nb], ah[mb], b.z, b.w);   // hi*lo
                mma_bf16(acc[mb][nb], al[mb], b.x, b.y);   // lo*hi
            }
        }
    }

    // epilogue: fp16 store
#pragma unroll
    for (int mb = 0; mb < 2; mb++) {
        int r = row0 + wy * 32 + mb * 16 + (lane >> 2);
#pragma unroll
        for (int nb = 0; nb < NB; nb++) {
            int c = v * NTILE + wx * (NTILE / 2) + nb * 8 + (lane & 3) * 2;
            if (r < MROWS)
                *(__half2*)&g_T[(ull)r * NTOT + c] = __floats2half2_rn(acc[mb][nb][0], acc[mb][nb][1]);
            if (r + 8 < MROWS)
                *(__half2*)&g_T[(ull)(r + 8) * NTOT + c] = __floats2half2_rn(acc[mb][nb][2], acc[mb][nb][3]);
        }
    }
}

// ---------------- sparse aggregation: one warp per node (fp16 workspace) ----------------
// acc = T[n, initOff..] + sum_edges w * T[src, srcOff..]   (fp32 accumulate)
// MODE 0: store acc (fp16) to T[n, outOff..]
// MODE 1: (C=128) s=sigmoid(acc+b); r-part -> r*hx bf16-split into g_Xs cols 64.., u-part -> g_U
// MODE 2: (C=64)  c=tanh(acc+b); out = u*hx + (1-u)*c  (fp32 out)
template <int C, int MODE>
__global__ void agg_kernel(int rowStride, int srcOff, int initOff, int outOff,
                           const float* __restrict__ bias,
                           const float* __restrict__ hx,
                           float* __restrict__ out) {
    constexpr int HV = C / 64;   // uint4 (8-half) chunks per lane
    const int warp = (blockIdx.x * blockDim.x + threadIdx.x) >> 5;
    const int lane = threadIdx.x & 31;
    if (warp >= NN) return;
    const int n = warp;

    int bq[HV], cq[HV];
#pragma unroll
    for (int q = 0; q < HV; q++) {
        int f = 8 * lane + 256 * q;
        bq[q] = f / C;
        cq[q] = bq[q] * rowStride + (f % C);
    }

    float accf[HV][8];
#pragma unroll
    for (int q = 0; q < HV; q++) {
        uint4 iv = *(const uint4*)&g_T[(ull)(n * 4) * rowStride + initOff + cq[q]];
        unpack8(iv, accf[q]);
    }

    const int beg = g_off[n];
    const int end = g_off[n + 1];
    int i = beg;
    for (; i + 1 < end; i += 2) {
        int s0 = g_csr_src[i];
        int s1 = g_csr_src[i + 1];
        float w0 = g_csr_w[i];
        float w1 = g_csr_w[i + 1];
        const __half* p0 = &g_T[(ull)(s0 * 4) * rowStride + srcOff];
        const __half* p1 = &g_T[(ull)(s1 * 4) * rowStride + srcOff];
        uint4 v0[HV], v1[HV];
#pragma unroll
        for (int q = 0; q < HV; q++) v0[q] = *(const uint4*)&p0[cq[q]];
#pragma unroll
        for (int q = 0; q < HV; q++) v1[q] = *(const uint4*)&p1[cq[q]];
#pragma unroll
        for (int q = 0; q < HV; q++) {
            float f0[8], f1[8];
            unpack8(v0[q], f0);
            unpack8(v1[q], f1);
#pragma unroll
            for (int t = 0; t < 8; t++) accf[q][t] += w0 * f0[t] + w1 * f1[t];
        }
    }
    if (i < end) {
        int s0 = g_csr_src[i];
        float w0 = g_csr_w[i];
        const __half* p0 = &g_T[(ull)(s0 * 4) * rowStride + srcOff];
#pragma unroll
        for (int q = 0; q < HV; q++) {
            float f0[8];
            unpack8(*(const uint4*)&p0[cq[q]], f0);
#pragma unroll
            for (int t = 0; t < 8; t++) accf[q][t] += w0 * f0[t];
        }
    }

    if (MODE == 0) {
#pragma unroll
        for (int q = 0; q < HV; q++) {
            uint4 o;
            __half2* oh = reinterpret_cast<__half2*>(&o);
#pragma unroll
            for (int t = 0; t < 4; t++)
                oh[t] = __floats2half2_rn(accf[q][2 * t], accf[q][2 * t + 1]);
            *(uint4*)&g_T[(ull)(n * 4) * rowStride + outOff + cq[q]] = o;
        }
    } else if (MODE == 1) {
        // C=128: b = 2q + (lane>=16), j = 8*(lane&15)
        const int jf = 8 * (lane & 15);
        float b8[8];
        *(float4*)&b8[0] = *(const float4*)&bias[jf];
        *(float4*)&b8[4] = *(const float4*)&bias[jf + 4];
#pragma unroll
        for (int q = 0; q < HV; q++) {
            int b = bq[q];
            float s[8];
#pragma unroll
            for (int t = 0; t < 8; t++)
                s[t] = 1.f / (1.f + expf(-(accf[q][t] + b8[t])));
            if (jf < 64) {
                // r part: write r*hx as bf16 split into g_Xs cols 64+jf
                float h8[8];
                *(float4*)&h8[0] = *(const float4*)&hx[(b * NN + n) * 64 + jf];
                *(float4*)&h8[4] = *(const float4*)&hx[(b * NN + n) * 64 + jf + 4];
                ushort4 oh[2], ol[2];
                ushort* ph = &oh[0].x;
                ushort* pl = &ol[0].x;
#pragma unroll
                for (int t = 0; t < 8; t++) split2(s[t] * h8[t], ph[t], pl[t]);
                ull base = (ull)(n * 4 + b) * 128 + 64 + jf;
                *(ushort4*)&g_Xs[0][base] = oh[0];
                *(ushort4*)&g_Xs[0][base + 4] = oh[1];
                *(ushort4*)&g_Xs[1][base] = ol[0];
                *(ushort4*)&g_Xs[1][base + 4] = ol[1];
            } else {
                int j = jf - 64;
                *(float4*)&g_U[(n * 4 + b) * 64 + j] = *(float4*)&s[0];
                *(float4*)&g_U[(n * 4 + b) * 64 + j + 4] = *(float4*)&s[4];
            }
        }
    } else {  // MODE 2, C=64: b = lane>>3, j = 8*(lane&7)
        const int b = lane >> 3;
        const int jf = 8 * (lane & 7);
        float b8[8], u8[8], h8[8];
        *(float4*)&b8[0] = *(const float4*)&bias[jf];
        *(float4*)&b8[4] = *(const float4*)&bias[jf + 4];
        *(float4*)&u8[0] = *(const float4*)&g_U[(n * 4 + b) * 64 + jf];
        *(float4*)&u8[4] = *(const float4*)&g_U[(n * 4 + b) * 64 + jf + 4];
        *(float4*)&h8[0] = *(const float4*)&hx[(b * NN + n) * 64 + jf];
        *(float4*)&h8[4] = *(const float4*)&hx[(b * NN + n) * 64 + jf + 4];
        float o8[8];
#pragma unroll
        for (int t = 0; t < 8; t++) {
            float c = tanhf(accf[0][t] + b8[t]);
            o8[t] = u8[t] * h8[t] + (1.f - u8[t]) * c;
        }
        *(float4*)&out[(b * NN + n) * 64 + jf] = *(float4*)&o8[0];
        *(float4*)&out[(b * NN + n) * 64 + jf + 4] = *(float4*)&o8[4];
    }
}

// ---------------- launch ----------------
extern "C" void kernel_launch(void* const* d_in, const int* in_sizes, int n_in,
                              void* d_out, int out_size) {
    const float* inputs = (const float*)d_in[0];
    const float* hx     = (const float*)d_in[1];
    const int*   sidx   = (const int*)d_in[2];
    const float* ker    = (const float*)d_in[3];
    const float* W_ru   = (const float*)d_in[4];
    const float* b_ru   = (const float*)d_in[5];
    const float* W_c    = (const float*)d_in[6];
    const float* b_c    = (const float*)d_in[7];
    float* out = (float*)d_out;
    const int* src = sidx;
    const int* dst = sidx + EE;

    const int SMEM_A = 2 * 128 * 272 + 8 * 16 * 32 * 16;  // 135168
    const int SMEM_B = 2 * 128 * 272 + 8 * 8 * 32 * 16;   // 102400
    cudaFuncSetAttribute(mma_gemm<128>, cudaFuncAttributeMaxDynamicSharedMemorySize, SMEM_A);
    cudaFuncSetAttribute(mma_gemm<64>,  cudaFuncAttributeMaxDynamicSharedMemorySize, SMEM_B);

    // CSR build
    zero_counts_kernel<<<(NN + 256) / 256, 256>>>();
    hist_kernel<<<(EE + 255) / 256, 256>>>(dst);
    scan_kernel<<<1, 1024>>>();
    fill_kernel<<<(EE + 255) / 256, 256>>>(src, dst, ker);

    // W fragment preprocessing
    wfrag_kernel<<<(8 * 384 * 4 + 8 * 192 * 4 + 255) / 256, 256>>>(W_ru, W_c);

    const int packBlocks = (MROWS * 32 + 255) / 256;

    // ---- phase A: ru gates ----
    packA_kernel<<<packBlocks, 256>>>(inputs, hx);
    mma_gemm<128><<<dim3(313, 3), 256, SMEM_A>>>();         // T = X @ [W0|W1|W2], 40000x384 fp16
    agg_kernel<128, 0><<<1250, 256>>>(384, 256, 128, 128, nullptr, nullptr, nullptr);
    agg_kernel<128, 1><<<1250, 256>>>(384, 128, 0, 0, b_ru, hx, nullptr);  // writes g_Xs + g_U

    // ---- phase B: candidate + GRU mix (packB folded into MODE 1) ----
    mma_gemm<64><<<dim3(313, 3), 256, SMEM_B>>>();          // T' = X' @ [W0'|W1'|W2'], 40000x192 fp16
    agg_kernel<64, 0><<<1250, 256>>>(192, 128, 64, 64, nullptr, nullptr, nullptr);
    agg_kernel<64, 2><<<1250, 256>>>(192, 64, 0, 0, b_c, hx, out);
}

// round 6
// speedup vs baseline: 1.8823x; 1.3421x over previous
#include <cuda_runtime.h>
#include <cuda_bf16.h>
#include <cuda_fp16.h>
#include <math.h>

#define NN 10000
#define BB 4
#define EE 160000
#define MROWS 40000   // N*B rows
#define MPAD  40064   // padded to 313*128

typedef unsigned long long ull;
typedef unsigned int uint;
typedef unsigned short ushort;

// ---------------- static scratch (no runtime allocation) ----------------
__device__ __align__(128) int   g_counts[NN + 1];
__device__ __align__(128) int   g_off[NN + 1];
__device__ __align__(128) int   g_cursor[NN];
__device__ __align__(128) int   g_csr_src[EE];
__device__ __align__(128) float g_csr_w[EE];
__device__ __align__(128) ushort g_Xs[2][(ull)MPAD * 128];   // bf16 hi/lo of X, [row][k]
__device__ __align__(128) uint4 g_Wruf[8 * 48 * 32];         // W_ru fragments [kt][n8][lane]
__device__ __align__(128) uint4 g_Wcf[8 * 24 * 32];          // W_c fragments
__device__ __align__(128) __half g_T[(ull)MROWS * 384];      // GEMM out / agg workspace (fp16)
__device__ __align__(128) float g_U[MROWS * 64];             // u gate [n][b][64]

// ---------------- helpers ----------------
__device__ __forceinline__ void split2(float a, ushort& hi, ushort& lo) {
    __nv_bfloat16 h = __float2bfloat16(a);
    __nv_bfloat16 l = __float2bfloat16(a - __bfloat162float(h));
    hi = *reinterpret_cast<ushort*>(&h);
    lo = *reinterpret_cast<ushort*>(&l);
}

__device__ __forceinline__ void mma_bf16(float* d, const uint* a, uint b0, uint b1) {
    asm volatile(
        "mma.sync.aligned.m16n8k16.row.col.f32.bf16.bf16.f32 "
        "{%0,%1,%2,%3}, {%4,%5,%6,%7}, {%8,%9}, {%0,%1,%2,%3};"
        : "+f"(d[0]), "+f"(d[1]), "+f"(d[2]), "+f"(d[3])
        : "r"(a[0]), "r"(a[1]), "r"(a[2]), "r"(a[3]), "r"(b0), "r"(b1));
}

__device__ __forceinline__ void unpack8(uint4 v, float* f) {
    const __half2* h = reinterpret_cast<const __half2*>(&v);
#pragma unroll
    for (int i = 0; i < 4; i++) {
        float2 t = __half22float2(h[i]);
        f[2 * i] = t.x;
        f[2 * i + 1] = t.y;
    }
}

__device__ __forceinline__ void fma8(float* acc, float w, uint4 v) {
    float f[8];
    unpack8(v, f);
#pragma unroll
    for (int t = 0; t < 8; t++) acc[t] += w * f[t];
}

// ---------------- CSR build ----------------
__global__ void zero_counts_kernel() {
    int i = blockIdx.x * blockDim.x + threadIdx.x;
    if (i <= NN) g_counts[i] = 0;
}

__global__ void hist_kernel(const int* __restrict__ dst) {
    int e = blockIdx.x * blockDim.x + threadIdx.x;
    if (e < EE) atomicAdd(&g_counts[dst[e]], 1);
}

__global__ void scan_kernel() {
    __shared__ int s[1024];
    const int t = threadIdx.x;
    const int base = t * 10;
    int vals[10];
    int run = 0;
#pragma unroll
    for (int i = 0; i < 10; i++) {
        int idx = base + i;
        int c = (idx < NN) ? g_counts[idx] : 0;
        run += c;
        vals[i] = run;
    }
    s[t] = run;
    __syncthreads();
    for (int d = 1; d < 1024; d <<= 1) {
        int v = (t >= d) ? s[t - d] : 0;
        __syncthreads();
        s[t] += v;
        __syncthreads();
    }
    int excl = s[t] - run;
    if (t == 0) g_off[0] = 0;
#pragma unroll
    for (int i = 0; i < 10; i++) {
        int idx = base + i;
        if (idx < NN) {
            g_off[idx + 1]  = excl + vals[i];
            g_cursor[idx]   = excl + (i ? vals[i - 1] : 0);
        }
    }
}

__global__ void fill_kernel(const int* __restrict__ src, const int* __restrict__ dst,
                            const float* __restrict__ ker) {
    int e = blockIdx.x * blockDim.x + threadIdx.x;
    if (e < EE) {
        int d = dst[e];
        int p = atomicAdd(&g_cursor[d], 1);
        g_csr_src[p] = src[e];
        g_csr_w[p]   = ker[e];
    }
}

// ---------------- input packing: B-major fp32 -> node-major bf16 hi/lo ----------------
__global__ void packA_kernel(const float* __restrict__ inputs, const float* __restrict__ hx) {
    int g = blockIdx.x * blockDim.x + threadIdx.x;  // one float4 each
    if (g >= MROWS * 32) return;
    int row = g >> 5;
    int k4  = (g & 31) * 4;
    int n = row >> 2, b = row & 3;
    float4 v;
    if (k4 < 64) v = *(const float4*)&inputs[(b * NN + n) * 64 + k4];
    else         v = *(const float4*)&hx[(b * NN + n) * 64 + (k4 - 64)];
    float av[4] = {v.x, v.y, v.z, v.w};
    ushort4 oh, ol;
    ushort* ph = &oh.x;
    ushort* pl = &ol.x;
#pragma unroll
    for (int i = 0; i < 4; i++) split2(av[i], ph[i], pl[i]);
    ull base = (ull)row * 128 + k4;
    *(ushort4*)&g_Xs[0][base] = oh;
    *(ushort4*)&g_Xs[1][base] = ol;
}

// ---------------- W -> fragment-order split (tiny, once per launch) ----------------
__global__ void wfrag_kernel(const float* __restrict__ W_ru, const float* __restrict__ W_c) {
    int idx = blockIdx.x * blockDim.x + threadIdx.x;
    const int T1 = 8 * 384 * 4;
    const int T2 = 8 * 192 * 4;
    if (idx < T1) {
        int kt = idx / (384 * 4);
        int rem = idx % (384 * 4);
        int n = rem >> 2, ksub = rem & 3;
        int v = n >> 7, j = n & 127;
        int k0 = kt * 16 + ksub * 2;
        float w0 = W_ru[(v * 128 + k0) * 128 + j];
        float w1 = W_ru[(v * 128 + k0 + 1) * 128 + j];
        float w8 = W_ru[(v * 128 + k0 + 8) * 128 + j];
        float w9 = W_ru[(v * 128 + k0 + 9) * 128 + j];
        ushort h0, l0, h1, l1, h8, l8, h9, l9;
        split2(w0, h0, l0); split2(w1, h1, l1);
        split2(w8, h8, l8); split2(w9, h9, l9);
        uint4 o;
        o.x = (uint)h0 | ((uint)h1 << 16);
        o.y = (uint)h8 | ((uint)h9 << 16);
        o.z = (uint)l0 | ((uint)l1 << 16);
        o.w = (uint)l8 | ((uint)l9 << 16);
        g_Wruf[(kt * 48 + (n >> 3)) * 32 + (n & 7) * 4 + ksub] = o;
    } else if (idx < T1 + T2) {
        int i2 = idx - T1;
        int kt = i2 / (192 * 4);
        int rem = i2 % (192 * 4);
        int n = rem >> 2, ksub = rem & 3;
        int v = n >> 6, j = n & 63;
        int k0 = kt * 16 + ksub * 2;
        float w0 = W_c[(v * 128 + k0) * 64 + j];
        float w1 = W_c[(v * 128 + k0 + 1) * 64 + j];
        float w8 = W_c[(v * 128 + k0 + 8) * 64 + j];
        float w9 = W_c[(v * 128 + k0 + 9) * 64 + j];
        ushort h0, l0, h1, l1, h8, l8, h9, l9;
        split2(w0, h0, l0); split2(w1, h1, l1);
        split2(w8, h8, l8); split2(w9, h9, l9);
        uint4 o;
        o.x = (uint)h0 | ((uint)h1 << 16);
        o.y = (uint)h8 | ((uint)h9 << 16);
        o.z = (uint)l0 | ((uint)l1 << 16);
        o.w = (uint)l8 | ((uint)l9 << 16);
        g_Wcf[(kt * 24 + (n >> 3)) * 32 + (n & 7) * 4 + ksub] = o;
    }
}

// ---------------- HMMA GEMM: T[M x 3*NTILE] = X @ Wcat, bf16x2 split (3 terms) ----------
// B operand read straight from global (L1-resident slice); only A staged in SMEM.
template <int NTILE>
__global__ __launch_bounds__(256, 2) void mma_gemm() {
    constexpr int NB = NTILE / 16;       // n8-blocks per warp
    constexpr int N8TOT = (NTILE == 128) ? 48 : 24;
    constexpr int NTOT = 3 * NTILE;
    constexpr int ASPLIT = 128 * 272;    // bytes per A split (272B padded rows)

    extern __shared__ __align__(16) char smem[];

    const int tid = threadIdx.x;
    const int wid = tid >> 5, lane = tid & 31;
    const int wx = wid & 1, wy = wid >> 1;
    const int row0 = blockIdx.x * 128;
    const int v = blockIdx.y;

    // stage A
    for (int it = tid; it < 2 * 128 * 16; it += 256) {
        int s = it >> 11, rem = it & 2047;
        int m = rem >> 4, q = rem & 15;
        uint4 val = *(const uint4*)&g_Xs[s][(ull)(row0 + m) * 128 + q * 8];
        *(uint4*)(smem + s * ASPLIT + m * 272 + q * 16) = val;
    }
    __syncthreads();

    const uint4* WF = (NTILE == 128) ? g_Wruf : g_Wcf;
    const int vbase = v * (NTILE / 8) + wx * NB;

    float acc[2][NB][4];
#pragma unroll
    for (int mb = 0; mb < 2; mb++)
#pragma unroll
        for (int nb = 0; nb < NB; nb++)
#pragma unroll
            for (int i = 0; i < 4; i++) acc[mb][nb][i] = 0.f;

#pragma unroll
    for (int kt = 0; kt < 8; kt++) {
        uint ah[2][4], al[2][4];
#pragma unroll
        for (int mb = 0; mb < 2; mb++) {
            int m = wy * 32 + mb * 16 + (lane >> 2);
            int boff = m * 272 + (kt * 16 + (lane & 3) * 2) * 2;
            ah[mb][0] = *(const uint*)(smem + boff);
            ah[mb][1] = *(const uint*)(smem + boff + 8 * 272);
            ah[mb][2] = *(const uint*)(smem + boff + 16);
            ah[mb][3] = *(const uint*)(smem + boff + 8 * 272 + 16);
            al[mb][0] = *(const uint*)(smem + ASPLIT + boff);
            al[mb][1] = *(const uint*)(smem + ASPLIT + boff + 8 * 272);
            al[mb][2] = *(const uint*)(smem + ASPLIT + boff + 16);
            al[mb][3] = *(const uint*)(smem + ASPLIT + boff + 8 * 272 + 16);
        }
#pragma unroll
        for (int nb = 0; nb < NB; nb++) {
            uint4 b = __ldg(&WF[(kt * N8TOT + vbase + nb) * 32 + lane]);
#pragma unroll
            for (int mb = 0; mb < 2; mb++) {
                mma_bf16(acc[mb][nb], ah[mb], b.x, b.y);   // hi*hi
                mma_bf16(acc[mb][nb], ah[mb], b.z, b.w);   // hi*lo
                mma_bf16(acc[mb][nb], al[mb], b.x, b.y);   // lo*hi
            }
        }
    }

    // epilogue: fp16 store
#pragma unroll
    for (int mb = 0; mb < 2; mb++) {
        int r = row0 + wy * 32 + mb * 16 + (lane >> 2);
#pragma unroll
        for (int nb = 0; nb < NB; nb++) {
            int c = v * NTILE + wx * (NTILE / 2) + nb * 8 + (lane & 3) * 2;
            if (r < MROWS)
                *(__half2*)&g_T[(ull)r * NTOT + c] = __floats2half2_rn(acc[mb][nb][0], acc[mb][nb][1]);
            if (r + 8 < MROWS)
                *(__half2*)&g_T[(ull)(r + 8) * NTOT + c] = __floats2half2_rn(acc[mb][nb][2], acc[mb][nb][3]);
        }
    }
}

// ---------------- sparse aggregation (fp16 workspace, fp32 accumulate) ----------------
// WPN warps per node (C=128 -> 2, C=64 -> 1); each lane owns 8 contiguous channels.
// MODE 0: store acc (fp16) to T[n, outOff..]
// MODE 1: (C=128) s=sigmoid(acc+b); j<64 -> r*hx bf16-split into g_Xs; j>=64 -> g_U
// MODE 2: (C=64)  c=tanh(acc+b); out = u*hx + (1-u)*c (fp32)
template <int C, int MODE, int WPN>
__global__ void agg_kernel(int rowStride, int srcOff, int initOff, int outOff,
                           const float* __restrict__ bias,
                           const float* __restrict__ hx,
                           float* __restrict__ out) {
    const int gw = (blockIdx.x * blockDim.x + threadIdx.x) >> 5;
    const int lane = threadIdx.x & 31;
    if (gw >= NN * WPN) return;
    const int n = (WPN == 2) ? (gw >> 1) : gw;
    const int h = (WPN == 2) ? (gw & 1) : 0;

    int b, j;
    if (C == 128) { b = 2 * h + (lane >> 4); j = 8 * (lane & 15); }
    else          { b = lane >> 3;           j = 8 * (lane & 7);  }
    const int cq = b * rowStride + j;

    float acc[8];
    unpack8(*(const uint4*)&g_T[(ull)(n * 4) * rowStride + initOff + cq], acc);

    const ull sb = (ull)srcOff + cq;
    const int beg = g_off[n];
    const int end = g_off[n + 1];
    int i = beg;
    for (; i + 3 < end; i += 4) {
        int s0 = g_csr_src[i],     s1 = g_csr_src[i + 1];
        int s2 = g_csr_src[i + 2], s3 = g_csr_src[i + 3];
        float w0 = g_csr_w[i],     w1 = g_csr_w[i + 1];
        float w2 = g_csr_w[i + 2], w3 = g_csr_w[i + 3];
        uint4 v0 = *(const uint4*)&g_T[(ull)(s0 * 4) * rowStride + sb];
        uint4 v1 = *(const uint4*)&g_T[(ull)(s1 * 4) * rowStride + sb];
        uint4 v2 = *(const uint4*)&g_T[(ull)(s2 * 4) * rowStride + sb];
        uint4 v3 = *(const uint4*)&g_T[(ull)(s3 * 4) * rowStride + sb];
        fma8(acc, w0, v0);
        fma8(acc, w1, v1);
        fma8(acc, w2, v2);
        fma8(acc, w3, v3);
    }
    for (; i < end; i++) {
        int s0 = g_csr_src[i];
        float w0 = g_csr_w[i];
        fma8(acc, w0, *(const uint4*)&g_T[(ull)(s0 * 4) * rowStride + sb]);
    }

    if (MODE == 0) {
        uint4 o;
        __half2* oh = reinterpret_cast<__half2*>(&o);
#pragma unroll
        for (int t = 0; t < 4; t++)
            oh[t] = __floats2half2_rn(acc[2 * t], acc[2 * t + 1]);
        *(uint4*)&g_T[(ull)(n * 4) * rowStride + outOff + cq] = o;
    } else if (MODE == 1) {
        float b8[8];
        *(float4*)&b8[0] = *(const float4*)&bias[j];
        *(float4*)&b8[4] = *(const float4*)&bias[j + 4];
        float s[8];
#pragma unroll
        for (int t = 0; t < 8; t++)
            s[t] = 1.f / (1.f + expf(-(acc[t] + b8[t])));
        if (j < 64) {
            // r part: write r*hx as bf16 split into g_Xs cols 64+j
            float h8[8];
            *(float4*)&h8[0] = *(const float4*)&hx[(b * NN + n) * 64 + j];
            *(float4*)&h8[4] = *(const float4*)&hx[(b * NN + n) * 64 + j + 4];
            ushort4 oh[2], ol[2];
            ushort* ph = &oh[0].x;
            ushort* pl = &ol[0].x;
#pragma unroll
            for (int t = 0; t < 8; t++) split2(s[t] * h8[t], ph[t], pl[t]);
            ull base = (ull)(n * 4 + b) * 128 + 64 + j;
            *(ushort4*)&g_Xs[0][base] = oh[0];
            *(ushort4*)&g_Xs[0][base + 4] = oh[1];
            *(ushort4*)&g_Xs[1][base] = ol[0];
            *(ushort4*)&g_Xs[1][base + 4] = ol[1];
        } else {
            int ju = j - 64;
            *(float4*)&g_U[(n * 4 + b) * 64 + ju] = *(float4*)&s[0];
            *(float4*)&g_U[(n * 4 + b) * 64 + ju + 4] = *(float4*)&s[4];
        }
    } else {  // MODE 2, C=64
        float b8[8], u8[8], h8[8];
        *(float4*)&b8[0] = *(const float4*)&bias[j];
        *(float4*)&b8[4] = *(const float4*)&bias[j + 4];
        *(float4*)&u8[0] = *(const float4*)&g_U[(n * 4 + b) * 64 + j];
        *(float4*)&u8[4] = *(const float4*)&g_U[(n * 4 + b) * 64 + j + 4];
        *(float4*)&h8[0] = *(const float4*)&hx[(b * NN + n) * 64 + j];
        *(float4*)&h8[4] = *(const float4*)&hx[(b * NN + n) * 64 + j + 4];
        float o8[8];
#pragma unroll
        for (int t = 0; t < 8; t++) {
            float c = tanhf(acc[t] + b8[t]);
            o8[t] = u8[t] * h8[t] + (1.f - u8[t]) * c;
        }
        *(float4*)&out[(b * NN + n) * 64 + j] = *(float4*)&o8[0];
        *(float4*)&out[(b * NN + n) * 64 + j + 4] = *(float4*)&o8[4];
    }
}

// ---------------- launch ----------------
extern "C" void kernel_launch(void* const* d_in, const int* in_sizes, int n_in,
                              void* d_out, int out_size) {
    const float* inputs = (const float*)d_in[0];
    const float* hx     = (const float*)d_in[1];
    const int*   sidx   = (const int*)d_in[2];
    const float* ker    = (const float*)d_in[3];
    const float* W_ru   = (const float*)d_in[4];
    const float* b_ru   = (const float*)d_in[5];
    const float* W_c    = (const float*)d_in[6];
    const float* b_c    = (const float*)d_in[7];
    float* out = (float*)d_out;
    const int* src = sidx;
    const int* dst = sidx + EE;

    const int SMEM = 2 * 128 * 272;   // 69632 (A only; B comes from global/L1)
    cudaFuncSetAttribute(mma_gemm<128>, cudaFuncAttributeMaxDynamicSharedMemorySize, SMEM);
    cudaFuncSetAttribute(mma_gemm<64>,  cudaFuncAttributeMaxDynamicSharedMemorySize, SMEM);

    // CSR build
    zero_counts_kernel<<<(NN + 256) / 256, 256>>>();
    hist_kernel<<<(EE + 255) / 256, 256>>>(dst);
    scan_kernel<<<1, 1024>>>();
    fill_kernel<<<(EE + 255) / 256, 256>>>(src, dst, ker);

    // W fragment preprocessing
    wfrag_kernel<<<(8 * 384 * 4 + 8 * 192 * 4 + 255) / 256, 256>>>(W_ru, W_c);

    const int packBlocks = (MROWS * 32 + 255) / 256;

    // ---- phase A: ru gates ----
    packA_kernel<<<packBlocks, 256>>>(inputs, hx);
    mma_gemm<128><<<dim3(313, 3), 256, SMEM>>>();           // T = X @ [W0|W1|W2], 40000x384 fp16
    agg_kernel<128, 0, 2><<<2500, 256>>>(384, 256, 128, 128, nullptr, nullptr, nullptr);
    agg_kernel<128, 1, 2><<<2500, 256>>>(384, 128, 0, 0, b_ru, hx, nullptr);  // writes g_Xs + g_U

    // ---- phase B: candidate + GRU mix ----
    mma_gemm<64><<<dim3(313, 3), 256, SMEM>>>();            // T' = X' @ [W0'|W1'|W2'], 40000x192 fp16
    agg_kernel<64, 0, 1><<<1250, 256>>>(192, 128, 64, 64, nullptr, nullptr, nullptr);
    agg_kernel<64, 2, 1><<<1250, 256>>>(192, 64, 0, 0, b_c, hx, out);
}